// round 15
// baseline (speedup 1.0000x reference)
#include <cuda_runtime.h>
#include <cuda_bf16.h>
#include <cstdint>

#define BATCH 32
#define SEQ   4096
#define EMBED 512
#define HID   256
#define OUTD  128
#define DECAYF 0.95f
#define LOG2_INV_D 0.07400058144377693f   // log2(1/0.95)

#define KSPLIT (3 * EMBED)                // 1536: A = (hi | hi | lo)

__device__ __nv_bfloat16 g_a3[SEQ * KSPLIT];    // A split   [4096][1536]
__device__ __nv_bfloat16 g_w1t[HID * KSPLIT];   // W1^T split [256][1536]: (hi|lo|hi)
__device__ float    g_curT[HID * SEQ];          // currents TRANSPOSED [256][4096]
__device__ float    g_cnt[HID];
__device__ unsigned g_done;

// ---------------------------------------------------------------------------
// Kernel 1: batch mean (emits split-bf16 A3) + fused W1 split prep (R14 exact).
// ---------------------------------------------------------------------------
__global__ void snn_mean_kernel(const float* __restrict__ x,
                                const float* __restrict__ W1) {
    if (blockIdx.x >= 2048) {                 // --- wprep part ---
        const int k = blockIdx.x - 2048;      // 0..511
        const int n = threadIdx.x;            // 0..255
        float v = W1[(size_t)k * HID + n];
        __nv_bfloat16 hi = __float2bfloat16(v);
        __nv_bfloat16 lo = __float2bfloat16(v - __bfloat162float(hi));
        g_w1t[(size_t)n * KSPLIT + k]             = hi;
        g_w1t[(size_t)n * KSPLIT + EMBED + k]     = lo;
        g_w1t[(size_t)n * KSPLIT + 2 * EMBED + k] = hi;
        return;
    }
    const int NF4 = (SEQ * EMBED) / 4;
    int i = blockIdx.x * blockDim.x + threadIdx.x;
    if (i >= NF4) return;
    const float4* x4 = reinterpret_cast<const float4*>(x);
    float sx = 0.f, sy = 0.f, sz = 0.f, sw = 0.f;
#pragma unroll
    for (int b = 0; b < BATCH; b++) {
        float4 v = x4[(size_t)b * NF4 + i];
        sx += v.x; sy += v.y; sz += v.z; sw += v.w;
    }
    const float inv = 1.0f / 32.0f;
    float v0 = sx * inv, v1 = sy * inv, v2 = sz * inv, v3 = sw * inv;

    __nv_bfloat16 h0 = __float2bfloat16(v0), h1 = __float2bfloat16(v1);
    __nv_bfloat16 h2 = __float2bfloat16(v2), h3 = __float2bfloat16(v3);
    __nv_bfloat16 l0 = __float2bfloat16(v0 - __bfloat162float(h0));
    __nv_bfloat16 l1 = __float2bfloat16(v1 - __bfloat162float(h1));
    __nv_bfloat16 l2 = __float2bfloat16(v2 - __bfloat162float(h2));
    __nv_bfloat16 l3 = __float2bfloat16(v3 - __bfloat162float(h3));

    __nv_bfloat162 ha = {h0, h1}, hb = {h2, h3};
    __nv_bfloat162 la = {l0, l1}, lb = {l2, l3};
    uint2 hu, lu;
    hu.x = *reinterpret_cast<unsigned*>(&ha); hu.y = *reinterpret_cast<unsigned*>(&hb);
    lu.x = *reinterpret_cast<unsigned*>(&la); lu.y = *reinterpret_cast<unsigned*>(&lb);

    const int s = i >> 7, d4 = i & 127;
    const size_t base = (size_t)s * KSPLIT + d4 * 4;
    *reinterpret_cast<uint2*>(&g_a3[base])             = hu;
    *reinterpret_cast<uint2*>(&g_a3[base + EMBED])     = hu;
    *reinterpret_cast<uint2*>(&g_a3[base + 2 * EMBED]) = lu;
}

// ---------------------------------------------------------------------------
// Kernel 2: HMMA bf16 GEMM (R14 exact).
// ---------------------------------------------------------------------------
#define MT 128
#define NT 64
#define KCH 64
#define NCH (KSPLIT / KCH)        // 24
#define APIT 72
#define SA_BYTES (MT * APIT * 2)  // 18432
#define SB_BYTES (NT * APIT * 2)  // 9216
#define SMB_OFF 36864
#define MMA_SMEM_BYTES 55296

__device__ __forceinline__ void cp16(unsigned dst, const void* src) {
    asm volatile("cp.async.cg.shared.global [%0], [%1], 16;" :: "r"(dst), "l"(src));
}
#define CP_COMMIT() asm volatile("cp.async.commit_group;")
#define CP_WAIT1()  asm volatile("cp.async.wait_group 1;")
#define CP_WAIT0()  asm volatile("cp.async.wait_group 0;")

__device__ __forceinline__ void mma16816(float& d0, float& d1, float& d2, float& d3,
                                         uint32_t a0, uint32_t a1, uint32_t a2, uint32_t a3,
                                         uint32_t b0, uint32_t b1) {
    asm volatile(
        "mma.sync.aligned.m16n8k16.row.col.f32.bf16.bf16.f32 "
        "{%0,%1,%2,%3}, {%4,%5,%6,%7}, {%8,%9}, {%0,%1,%2,%3};"
        : "+f"(d0), "+f"(d1), "+f"(d2), "+f"(d3)
        : "r"(a0), "r"(a1), "r"(a2), "r"(a3), "r"(b0), "r"(b1));
}

__global__ void __launch_bounds__(256, 1)
snn_mma_kernel(void) {
    extern __shared__ char smem[];
    const unsigned sb = (unsigned)__cvta_generic_to_shared(smem);
    __nv_bfloat16* sm16 = reinterpret_cast<__nv_bfloat16*>(smem);

    const int tid  = threadIdx.x;
    const int wid  = tid >> 5;
    const int lane = tid & 31;
    const int g = lane >> 2;
    const int t = lane & 3;
    const int warp_m = wid >> 1;
    const int warp_n = wid & 1;
    const int s0 = blockIdx.x * MT;
    const int h0 = blockIdx.y * NT;

    auto load_chunk = [&](int c, int buf) {
        const __nv_bfloat16* As = &g_a3[(size_t)s0 * KSPLIT + c * KCH];
        unsigned dA = sb + buf * SA_BYTES;
#pragma unroll
        for (int l = 0; l < 4; l++) {
            int f = tid + l * 256;
            int r = f >> 3, sg = f & 7;
            cp16(dA + r * (APIT * 2) + sg * 16, As + (size_t)r * KSPLIT + sg * 8);
        }
        const __nv_bfloat16* Bs = &g_w1t[(size_t)h0 * KSPLIT + c * KCH];
        unsigned dB = sb + SMB_OFF + buf * SB_BYTES;
#pragma unroll
        for (int l = 0; l < 2; l++) {
            int f = tid + l * 256;
            int r = f >> 3, sg = f & 7;
            cp16(dB + r * (APIT * 2) + sg * 16, Bs + (size_t)r * KSPLIT + sg * 8);
        }
        CP_COMMIT();
    };

    float acc[2][4][4];
#pragma unroll
    for (int i = 0; i < 2; i++)
#pragma unroll
        for (int j = 0; j < 4; j++)
#pragma unroll
            for (int r = 0; r < 4; r++) acc[i][j][r] = 0.f;

    load_chunk(0, 0);
    load_chunk(1, 1);

#pragma unroll 1
    for (int c = 0; c < NCH; c++) {
        if (c + 1 < NCH) CP_WAIT1(); else CP_WAIT0();
        __syncthreads();

        const int buf = c & 1;
        const __nv_bfloat16* A = sm16 + buf * (SA_BYTES / 2);
        const __nv_bfloat16* B = sm16 + (SMB_OFF / 2) + buf * (SB_BYTES / 2);

#pragma unroll
        for (int ks = 0; ks < KCH / 16; ks++) {
            const int kb = ks * 16;
            uint32_t af[2][4];
#pragma unroll
            for (int mf = 0; mf < 2; mf++) {
                const int rb = warp_m * 32 + mf * 16;
                af[mf][0] = *reinterpret_cast<const uint32_t*>(&A[(rb + g)     * APIT + kb + t * 2]);
                af[mf][1] = *reinterpret_cast<const uint32_t*>(&A[(rb + g + 8) * APIT + kb + t * 2]);
                af[mf][2] = *reinterpret_cast<const uint32_t*>(&A[(rb + g)     * APIT + kb + t * 2 + 8]);
                af[mf][3] = *reinterpret_cast<const uint32_t*>(&A[(rb + g + 8) * APIT + kb + t * 2 + 8]);
            }
            uint32_t bf[4][2];
#pragma unroll
            for (int nf = 0; nf < 4; nf++) {
                const int nr = warp_n * 32 + nf * 8 + g;
                bf[nf][0] = *reinterpret_cast<const uint32_t*>(&B[nr * APIT + kb + t * 2]);
                bf[nf][1] = *reinterpret_cast<const uint32_t*>(&B[nr * APIT + kb + t * 2 + 8]);
            }
#pragma unroll
            for (int mf = 0; mf < 2; mf++)
#pragma unroll
                for (int nf = 0; nf < 4; nf++)
                    mma16816(acc[mf][nf][0], acc[mf][nf][1], acc[mf][nf][2], acc[mf][nf][3],
                             af[mf][0], af[mf][1], af[mf][2], af[mf][3],
                             bf[nf][0], bf[nf][1]);
        }
        __syncthreads();
        if (c + 2 < NCH) load_chunk(c + 2, buf);
    }

    float* sT = reinterpret_cast<float*>(smem);   // [64][132]
#pragma unroll
    for (int mf = 0; mf < 2; mf++) {
        const int mb = warp_m * 32 + mf * 16;
#pragma unroll
        for (int nf = 0; nf < 4; nf++) {
            const int nb = warp_n * 32 + nf * 8 + t * 2;
            sT[(nb + 0) * 132 + mb + g]     = acc[mf][nf][0];
            sT[(nb + 1) * 132 + mb + g]     = acc[mf][nf][1];
            sT[(nb + 0) * 132 + mb + g + 8] = acc[mf][nf][2];
            sT[(nb + 1) * 132 + mb + g + 8] = acc[mf][nf][3];
        }
    }
    __syncthreads();
#pragma unroll
    for (int l = 0; l < 8; l++) {
        int f    = tid + l * 256;
        int hrow = f >> 5;
        int seg  = f & 31;
        float4 v = *reinterpret_cast<float4*>(&sT[hrow * 132 + seg * 4]);
        *reinterpret_cast<float4*>(
            &g_curT[(size_t)(h0 + hrow) * SEQ + s0 + seg * 4]) = v;
    }
}

// ---------------------------------------------------------------------------
// Kernel 3: LIF scan with GROUP COMPOSITION (G=4 windows).
// Phase A : per-window records (R14-validated) + prefix-max PM stored.
//           meta = count<<4 | carryFlag<<2 | o;  Xn = CONT threshold.
// Phase A2: suffix-compose records within each 4-window group (in place),
//           so S_w[r] covers restart r of window w through group end.
// Phase B : 32 group iterations; carry entry = 1 lookup; CONT entry =
//           5-shfl binary search on PM + 1 lookup. Bit-identical counts.
// ---------------------------------------------------------------------------
#define SCAN_SMEM_FLOATS (3 * SEQ + 128)
#define SCAN_SMEM_BYTES  (SCAN_SMEM_FLOATS * 4)
#define FULLW 0xffffffffu

__global__ void __launch_bounds__(256, 1)
snn_scan_kernel(const float* __restrict__ W2, float* __restrict__ out) {
    extern __shared__ float ssm[];
    float*    sPM  = ssm;                                   // [4096]
    unsigned* sMt  = reinterpret_cast<unsigned*>(ssm + SEQ);// [4096]
    float*    sXn  = ssm + 2 * SEQ;                         // [4096]
    float*    sC1  = ssm + 3 * SEQ;                         // [128]
    __shared__ unsigned slast;

    const int h    = blockIdx.x;
    const int tid  = threadIdx.x;
    const int lane = tid & 31;
    const int warp = tid >> 5;

    const float dinv = exp2f((float)lane * LOG2_INV_D);   // d^{-lane}
    const float d31  = exp2f(-31.0f * LOG2_INV_D);        // d^31
    const float C2   = DECAYF * d31;                      // no-spike X multiplier

    // ===== Phase A =====
#pragma unroll 1
    for (int win = warp; win < SEQ / 32; win += 8) {
        float c = g_curT[(size_t)h * SEQ + win * 32 + lane];
        float p = c * dinv;
#pragma unroll
        for (int off = 1; off < 32; off <<= 1) {
            float v = __shfl_up_sync(FULLW, p, off);
            if (lane >= off) p += v;
        }
        float Q  = p - dinv;
        float pv = __shfl_up_sync(FULLW, p, 1);
        float XR = (lane == 0) ? 0.f : pv;                // P_{lane-1}

        float M0 = Q;
        float M1 = fmaxf(M0, __shfl_down_sync(FULLW, M0, 1));
        float M2 = fmaxf(M1, __shfl_down_sync(FULLW, M1, 2));
        float M3 = fmaxf(M2, __shfl_down_sync(FULLW, M2, 4));
        float M4 = fmaxf(M3, __shfl_down_sync(FULLW, M3, 8));
        float M5 = fmaxf(M4, __shfl_down_sync(FULLW, M4, 16));

        const float X = XR;
        const bool exists = (M5 >= X);
        int pos = lane;
        {
            float mk;
            mk = __shfl_sync(FULLW, M4, pos & 31); if (mk < X) pos += 16;
            mk = __shfl_sync(FULLW, M3, pos & 31); if (mk < X) pos += 8;
            mk = __shfl_sync(FULLW, M2, pos & 31); if (mk < X) pos += 4;
            mk = __shfl_sync(FULLW, M1, pos & 31); if (mk < X) pos += 2;
            mk = __shfl_sync(FULLW, M0, pos & 31); if (mk < X) pos += 1;
        }
        unsigned st;
        if (!exists)         st = (2u << 5) | (unsigned)lane;
        else if (pos <= 28)  st = (1u << 7) | (0u << 5) | (unsigned)(pos + 3);
        else                 st = (1u << 7) | (1u << 5) | (unsigned)(pos - 29);

#pragma unroll
        for (int r = 0; r < 4; r++) {
            unsigned s2 = __shfl_sync(FULLW, st, st & 31);
            if (((st >> 5) & 3u) == 0u)
                st = (((st >> 7) + (s2 >> 7)) << 7) | (s2 & 0x7Fu);
        }

        // compose per-window exit record
        const unsigned cntw = st >> 7;
        const unsigned term = (st >> 5) & 3u;
        const unsigned p5   = st & 31u;
        const float P31 = __shfl_sync(FULLW, p, 31);
        const float xr  = __shfl_sync(FULLW, XR, p5);
        const float Xn  = -DECAYF * (d31 * (P31 - xr));
        unsigned meta;
        if (term == 1u) meta = (cntw << 4) | 4u | p5;   // carry exit, o=p5 (0..2)
        else            meta = (cntw << 4);             // CONT exit

        // prefix max of Q
        float pm = Q;
#pragma unroll
        for (int off = 1; off < 32; off <<= 1) {
            float v = __shfl_up_sync(FULLW, pm, off);
            if (lane >= off) pm = fmaxf(pm, v);
        }

        sPM[win * 32 + lane] = pm;
        sMt[win * 32 + lane] = meta;
        sXn[win * 32 + lane] = Xn;
        if (lane == 31) sC1[win] = -DECAYF * d31 * p;   // -d*d31*P31
    }
    __syncthreads();

    // ===== Phase A2: suffix composition within 4-window groups =====
#pragma unroll 1
    for (int j = 0; j < 4; j++) {
        const int b = (warp * 4 + j) * 4;               // group base window
#pragma unroll 1
        for (int w = b + 2; w >= b; w--) {
            unsigned m  = sMt[w * 32 + lane];
            float    xn = sXn[w * 32 + lane];
            int   cnt = (int)(m >> 4);
            int   carry = (int)((m >> 2) & 1u);
            int   o = (int)(m & 3u);
            float X = xn;
            int resolved = 0;
            unsigned outM = 0; float outX = 0.f;
#pragma unroll 1
            for (int u = w + 1; u <= b + 3; u++) {
                float    pm_u = sPM[u * 32 + lane];
                unsigned su_m = sMt[u * 32 + lane];
                float    su_x = sXn[u * 32 + lane];
                float    c1   = sC1[u];
                unsigned lmC = __shfl_sync(FULLW, su_m, o);
                float    lxC = __shfl_sync(FULLW, su_x, o);
                float pmTop = __shfl_sync(FULLW, pm_u, 31);
                int t = 0; float v;
                v = __shfl_sync(FULLW, pm_u, 15);    if (v < X) t = 16;
                v = __shfl_sync(FULLW, pm_u, t + 7); if (v < X) t += 8;
                v = __shfl_sync(FULLW, pm_u, t + 3); if (v < X) t += 4;
                v = __shfl_sync(FULLW, pm_u, t + 1); if (v < X) t += 2;
                v = __shfl_sync(FULLW, pm_u, t);     if (v < X) t += 1;
                int tl = (t + 3 > 31) ? 31 : t + 3;
                unsigned lmS = __shfl_sync(FULLW, su_m, tl);
                float    lxS = __shfl_sync(FULLW, su_x, tl);
                if (!resolved) {
                    if (carry) {
                        outM = ((unsigned)(cnt + (int)(lmC >> 4)) << 4) | (lmC & 7u);
                        outX = lxC; resolved = 1;
                    } else if (pmTop >= X) {
                        cnt += 1;
                        if (t <= 28) {
                            outM = ((unsigned)(cnt + (int)(lmS >> 4)) << 4) | (lmS & 7u);
                            outX = lxS; resolved = 1;
                        } else {
                            carry = 1; o = t - 29;
                            if (u == b + 3) {
                                outM = ((unsigned)cnt << 4) | 4u | (unsigned)o;
                                resolved = 1;
                            }
                        }
                    } else {
                        X = fmaf(C2, X, c1);
                        if (u == b + 3) {
                            outM = ((unsigned)cnt << 4); outX = X; resolved = 1;
                        }
                    }
                }
            }
            __syncwarp();
            sMt[w * 32 + lane] = outM;
            sXn[w * 32 + lane] = outX;
            __syncwarp();
        }
    }
    __syncthreads();

    // ===== Phase B (warp 0): 32 group iterations =====
    if (warp == 0) {
        int cnt = 0, carry = 1, o = 0;
        float X = 0.f;
#pragma unroll 1
        for (int gi = 0; gi < 32; gi++) {
            const int base = gi * 4;
            float    pm = sPM[base * 32 + lane];
            unsigned sm = sMt[base * 32 + lane];
            float    sx = sXn[base * 32 + lane];
            if (carry) {
                unsigned lm = __shfl_sync(FULLW, sm, o);
                float    lx = __shfl_sync(FULLW, sx, o);
                cnt += (int)(lm >> 4);
                carry = (int)((lm >> 2) & 1u); o = (int)(lm & 3u); X = lx;
            } else {
                int u = base;
                for (;;) {
                    float pmTop = __shfl_sync(FULLW, pm, 31);
                    int t = 0; float v;
                    v = __shfl_sync(FULLW, pm, 15);    if (v < X) t = 16;
                    v = __shfl_sync(FULLW, pm, t + 7); if (v < X) t += 8;
                    v = __shfl_sync(FULLW, pm, t + 3); if (v < X) t += 4;
                    v = __shfl_sync(FULLW, pm, t + 1); if (v < X) t += 2;
                    v = __shfl_sync(FULLW, pm, t);     if (v < X) t += 1;
                    if (pmTop >= X) {
                        cnt += 1;
                        if (t <= 28) {
                            unsigned lm = __shfl_sync(FULLW, sm, t + 3);
                            float    lx = __shfl_sync(FULLW, sx, t + 3);
                            cnt += (int)(lm >> 4);
                            carry = (int)((lm >> 2) & 1u); o = (int)(lm & 3u); X = lx;
                            break;
                        } else {
                            o = t - 29;
                            if (u == base + 3) { carry = 1; break; }
                            u++;
                            sm = sMt[u * 32 + lane]; sx = sXn[u * 32 + lane];
                            unsigned lm = __shfl_sync(FULLW, sm, o);
                            float    lx = __shfl_sync(FULLW, sx, o);
                            cnt += (int)(lm >> 4);
                            carry = (int)((lm >> 2) & 1u); o = (int)(lm & 3u); X = lx;
                            break;
                        }
                    } else {
                        X = fmaf(C2, X, sC1[u]);
                        if (u == base + 3) { carry = 0; break; }
                        u++;
                        pm = sPM[u * 32 + lane];
                        sm = sMt[u * 32 + lane]; sx = sXn[u * 32 + lane];
                    }
                }
            }
        }
        if (lane == 0) g_cnt[h] = (float)cnt;
    }
    __syncthreads();
    __threadfence();
    if (tid == 0) slast = atomicAdd(&g_done, 1u);
    __syncthreads();

    if (slast == HID - 1 && tid < OUTD) {
        __threadfence();
        volatile float* vc = g_cnt;
        float a = 0.f;
#pragma unroll 16
        for (int k = 0; k < HID; k++)
            a += vc[k] * W2[(size_t)k * OUTD + tid];
        a *= (1.0f / (float)SEQ);
#pragma unroll
        for (int b = 0; b < BATCH; b++)
            out[(size_t)b * OUTD + tid] = a;
        __threadfence();
        if (tid == 0) g_done = 0;
    }
}

// ---------------------------------------------------------------------------
extern "C" void kernel_launch(void* const* d_in, const int* in_sizes, int n_in,
                              void* d_out, int out_size) {
    const float* x  = (const float*)d_in[0];   // [32][4096][512]
    const float* w1 = (const float*)d_in[1];   // [512][256]
    const float* w2 = (const float*)d_in[2];   // [256][128]
    float* out = (float*)d_out;                // [32][128]

    cudaFuncSetAttribute(snn_mma_kernel,
                         cudaFuncAttributeMaxDynamicSharedMemorySize,
                         MMA_SMEM_BYTES);
    cudaFuncSetAttribute(snn_scan_kernel,
                         cudaFuncAttributeMaxDynamicSharedMemorySize,
                         SCAN_SMEM_BYTES);

    snn_mean_kernel<<<2048 + EMBED, 256>>>(x, w1);
    snn_mma_kernel<<<dim3(SEQ / MT, HID / NT), 256, MMA_SMEM_BYTES>>>();
    snn_scan_kernel<<<HID, 256, SCAN_SMEM_BYTES>>>(w2, out);
}